// round 12
// baseline (speedup 1.0000x reference)
#include <cuda_runtime.h>
#include <cstdint>

// Fixed shapes: B=16, K=64, H=96, W=96
constexpr int B = 16;
constexpr int K = 64;
constexpr int H = 96;
constexpr int W = 96;
constexpr int IMG = H * W;                      // 9216
constexpr int NSTACK = B * K;                   // 1024
constexpr long long NBIG = (long long)B * K * H * W;
constexpr int KP_ELEMS = B * 3 * K * 2;         // 6144
constexpr int ZETA_ELEMS = B * K;               // 1024

constexpr int THREADS = 256;                    // 8 warps
constexpr int NCHUNK = 3;                       // 3 chunks of 32 rows per tile
constexpr int CH_ROWS  = H / NCHUNK;            // 32
constexpr int CH_ELEMS = CH_ROWS * W;           // 3072 floats
constexpr int CH_BYTES = CH_ELEMS * 4;          // 12288 B
constexpr int CH_V4    = CH_ELEMS / 4;          // 768 float4
constexpr int CH_ITERS = CH_V4 / THREADS;       // 3

constexpr int NTILES = 2 * NSTACK;              // 2048 (stack x {Rk, tf_Rk})
constexpr int GRID = 444;                       // 3 blocks/SM x 148 SMs
constexpr int NBUF = 2 * NCHUNK;                // double-buffered chunk sets
constexpr int SMEM_DYN = NBUF * CH_BYTES;       // 73728 B

// sigmoid with div.approx (MUFU.RCP + FMUL); rel err ~2e-7 << 1e-3 gate
__device__ __forceinline__ float sigmoidf(float x) {
    return __fdividef(1.0f, 1.0f + __expf(-x));
}

// mbarrier wait with HW sleep hint — no hot-spin issue theft
__device__ __forceinline__ void mbar_wait(uint32_t msa, uint32_t parity) {
    uint32_t done;
    asm volatile(
        "{\n\t.reg .pred p;\n\t"
        "mbarrier.try_wait.parity.acquire.cta.shared::cta.b64 p, [%1], %2;\n\t"
        "selp.b32 %0, 1, 0, p;\n\t}"
        : "=r"(done) : "r"(msa), "r"(parity) : "memory");
    if (!done) {
        asm volatile(
            "{\n\t.reg .pred P1;\n\t"
            "WAIT_LOOP_%=:\n\t"
            "mbarrier.try_wait.parity.acquire.cta.shared::cta.b64 P1, [%0], %1, 0x989680;\n\t"
            "@P1 bra.uni WAIT_DONE_%=;\n\t"
            "bra.uni WAIT_LOOP_%=;\n\t"
            "WAIT_DONE_%=:\n\t}"
            :: "r"(msa), "r"(parity) : "memory");
    }
}

__global__ __launch_bounds__(THREADS)
void fused_decode_kernel(const float* __restrict__ Rk,
                         const float* __restrict__ tfRk,
                         float* __restrict__ Dk_out,
                         float* __restrict__ tfDk_out,
                         float* __restrict__ kp_out,
                         float* __restrict__ tfkp_out,
                         float* __restrict__ zeta_out,
                         float* __restrict__ tfzeta_out)
{
    extern __shared__ float buf[];                 // [NBUF][CH_ELEMS]
    __shared__ alignas(8) unsigned long long mbar[NBUF];
    __shared__ float sm0[8], smx[8], smy[8];

    const int tid = threadIdx.x;
    const int lane = tid & 31;
    const int warp = tid >> 5;

    if (tid < NBUF) {
        const uint32_t msa = (uint32_t)__cvta_generic_to_shared(&mbar[tid]);
        asm volatile("mbarrier.init.shared.b64 [%0], %1;" :: "r"(msa), "r"(1) : "memory");
    }
    __syncthreads();

    // L2 policies: input reads evict_first; output writes evict_last
    // (write-only output rewritten every replay -> stays resident in L2).
    uint64_t pol_ef, pol_el;
    asm volatile("createpolicy.fractional.L2::evict_first.b64 %0, 1.0;" : "=l"(pol_ef));
    asm volatile("createpolicy.fractional.L2::evict_last.b64 %0, 1.0;"  : "=l"(pol_el));

    // Issue the 3 chunk TMA loads of tile j into buffer set `set`
    auto issue_tile = [&](int j, int set) {
        const int jwhich = j >> 10;
        const int jstack = j & (NSTACK - 1);
        const float* src = (jwhich ? tfRk : Rk) + (size_t)jstack * IMG;
#pragma unroll
        for (int c = 0; c < NCHUNK; ++c) {
            const int bi = set * NCHUNK + c;
            const uint32_t msa = (uint32_t)__cvta_generic_to_shared(&mbar[bi]);
            const uint32_t bsa = (uint32_t)__cvta_generic_to_shared(buf + bi * CH_ELEMS);
            asm volatile("mbarrier.arrive.expect_tx.shared.b64 _, [%0], %1;"
                         :: "r"(msa), "r"(CH_BYTES) : "memory");
            asm volatile("cp.async.bulk.shared::cta.global.mbarrier::complete_tx::bytes.L2::cache_hint "
                         "[%0], [%1], %2, [%3], %4;"
                         :: "r"(bsa), "l"(src + c * CH_ELEMS), "r"(CH_BYTES),
                            "r"(msa), "l"(pol_ef)
                         : "memory");
        }
    };

    int tile = blockIdx.x;
    int i = 0;                                    // local iteration counter

    if (tid == 0) issue_tile(tile, 0);            // prologue: tile0 -> set 0

    while (tile < NTILES) {
        const int set = i & 1;
        const uint32_t par = (uint32_t)((i >> 1) & 1);
        const int which = tile >> 10;
        const int stack = tile & (NSTACK - 1);
        float* __restrict__ D = (which ? tfDk_out : Dk_out) + (size_t)stack * IMG;

        // Prefetch next tile into the other set. wait_group 0 first: drains
        // the other set's bulk stores (from tile i-1) so its buffers are free.
        // Other warps are already computing chunk 0 meanwhile.
        if (tid == 0) {
            const int nt = tile + GRID;
            if (nt < NTILES) {
                asm volatile("cp.async.bulk.wait_group 0;" ::: "memory");
                issue_tile(nt, (i + 1) & 1);
            }
        }

        float s0 = 0.0f, sx = 0.0f, sy = 0.0f;

#pragma unroll
        for (int c = 0; c < NCHUNK; ++c) {
            const int bi = set * NCHUNK + c;
            mbar_wait((uint32_t)__cvta_generic_to_shared(&mbar[bi]), par);

            float4* __restrict__ T4 = reinterpret_cast<float4*>(buf + bi * CH_ELEMS);

#pragma unroll
            for (int it = 0; it < CH_ITERS; ++it) {
                const int v = tid + it * THREADS;     // float4 index within chunk
                float4 r = T4[v];
                float4 d;
                d.x = sigmoidf(r.x);
                d.y = sigmoidf(r.y);
                d.z = sigmoidf(r.z);
                d.w = sigmoidf(r.w);
                T4[v] = d;                            // sigmoid in place

                const int e = v * 4;
                const int hl = e / W;
                const int w = e - hl * W;
                const int h = hl + c * CH_ROWS;
                const float rowsum = (d.x + d.y) + (d.z + d.w);
                s0 += rowsum;
                sy += rowsum * (float)h;
                sx += fmaf((float)w, rowsum, fmaf(3.0f, d.w, fmaf(2.0f, d.z, d.y)));
            }

            __syncthreads();                          // chunk fully sigmoided in smem
            if (tid == 0) {
                const uint32_t bsa = (uint32_t)__cvta_generic_to_shared(buf + bi * CH_ELEMS);
                asm volatile("fence.proxy.async.shared::cta;" ::: "memory");
                asm volatile("cp.async.bulk.global.shared::cta.bulk_group.L2::cache_hint "
                             "[%0], [%1], %2, %3;"
                             :: "l"(D + c * CH_ELEMS), "r"(bsa), "r"(CH_BYTES), "l"(pol_el)
                             : "memory");
                asm volatile("cp.async.bulk.commit_group;" ::: "memory");
            }
        }

        // ---- block reduction + keypoint ----
#pragma unroll
        for (int o = 16; o > 0; o >>= 1) {
            s0 += __shfl_down_sync(0xffffffffu, s0, o);
            sx += __shfl_down_sync(0xffffffffu, sx, o);
            sy += __shfl_down_sync(0xffffffffu, sy, o);
        }
        if (lane == 0) { sm0[warp] = s0; smx[warp] = sx; smy[warp] = sy; }
        __syncthreads();

        if (tid == 0) {
            float z = 0.0f, fx = 0.0f, fy = 0.0f;
#pragma unroll
            for (int j = 0; j < 8; ++j) { z += sm0[j]; fx += smx[j]; fy += smy[j]; }

            // Full-precision div: kx/ky feed rintf (round-half-even, = jnp.round)
            const float kx = rintf(fx / z);
            const float ky = rintf(fy / z);
            const int wi = (int)kx;
            const int hi = (int)ky;

            // smem of the CURRENT set still holds the sigmoided map (it isn't
            // overwritten until iteration i+1 issues tile i+2's loads).
            const int ch = hi / CH_ROWS;
            const float dloc = buf[(set * NCHUNK + ch) * CH_ELEMS + (hi - ch * CH_ROWS) * W + wi];

            const int b = stack / K;
            const int k = stack - b * K;
            float* kp_base   = (which ? tfkp_out : kp_out);
            float* zeta_base = (which ? tfzeta_out : zeta_out);

            float* kp  = kp_base + ((size_t)b * (3 * K) + k) * 2;
            float* kp1 = kp_base + ((size_t)b * (3 * K) + K + k) * 2;
            float* kp2 = kp_base + ((size_t)b * (3 * K) + 2 * K + k) * 2;
            kp[0]  = kx;
            kp[1]  = ky;
            kp1[0] = truncf(kx + kx * dloc);
            kp1[1] = truncf(ky + ky * dloc);
            kp2[0] = truncf(kx - kx * dloc);
            kp2[1] = truncf(ky - ky * dloc);

            zeta_base[stack] = z;
        }

        tile += GRID;
        ++i;
    }

    // Drain outstanding bulk stores before exit.
    if (tid == 0) {
        asm volatile("cp.async.bulk.wait_group 0;" ::: "memory");
    }
}

extern "C" void kernel_launch(void* const* d_in, const int* in_sizes, int n_in,
                              void* d_out, int out_size)
{
    const float* Rk   = (const float*)d_in[0];
    const float* tfRk = (const float*)d_in[1];

    float* out = (float*)d_out;
    float* Dk     = out;
    float* tfDk   = out + NBIG;
    float* kp     = out + 2 * NBIG;
    float* tfkp   = kp + KP_ELEMS;
    float* zeta   = tfkp + KP_ELEMS;
    float* tfzeta = zeta + ZETA_ELEMS;

    // 72 KB dynamic smem needs explicit opt-in (static limit is 48 KB)
    cudaFuncSetAttribute(fused_decode_kernel,
                         cudaFuncAttributeMaxDynamicSharedMemorySize, SMEM_DYN);

    fused_decode_kernel<<<GRID, THREADS, SMEM_DYN>>>(Rk, tfRk, Dk, tfDk,
                                                     kp, tfkp, zeta, tfzeta);
}